// round 14
// baseline (speedup 1.0000x reference)
#include <cuda_runtime.h>
#include <cuda_bf16.h>
#include <math.h>
#include <stdint.h>

#define BB 8
#define NN 256
#define KK 128
#define HH 32
#define EMB 768
#define FD 768

#define GAB_ELEMS   (BB*HH*NN*NN)      // 16777216
#define MEF_ELEMS   (BB*NN*EMB)        // 1572864

// scratch (no cudaMalloc allowed)
__device__ float g_sumef4[4 * BB * NN * KK];   // [jq][b*N+i][k]
__device__ int   g_pad[BB * NN];
// pre-packed mma B-fragments (bf16 hi/lo pairs), exact lane order
__device__ uint2 g_B1hi[4096], g_B1lo[4096];   // [(s*16+nb)*32 + lane]
__device__ uint2 g_B2hi[1024], g_B2lo[1024];   // [(s*4+nb)*32 + lane]

// ---------------------------------------------------------------------------
// SMEM layout (bytes), 256-thread block, 64 j rows:
//   A   : ef chunk bf16-pairs [64 j][20]  (16 kpairs + 4 pad) hi/lo
//   G   : gelu bf16-pairs     [64 j][68]  (64 hpairs + 4 pad) hi/lo
//   CST : C2 staging fp32     [64 j][37]
//   A aliases inside G-hi; CST aliases G-hi (all windows barrier-fenced)
// ---------------------------------------------------------------------------
#define GHIO   0         // 17408
#define GLOO   17408     // 17408 -> 34816
#define AHIO   0         // 5120 (inside G-hi, dead before G written)
#define ALOO   5120      // 5120 -> 10240
#define CSTO   0         // 9472 (over G-hi, after GEMM2)
#define TSOF   34816     // 256
#define KEEPO  35072     // 256
#define SPARTO 35328     // 2048 (256 x float2)
#define SMEM_TOTAL 37376

// ---------------------------------------------------------------------------
__device__ __forceinline__ uint32_t smem_u32(const void* p) {
    uint32_t a;
    asm("{ .reg .u64 t; cvta.to.shared.u64 t, %1; cvt.u32.u64 %0, t; }"
        : "=r"(a) : "l"(p));
    return a;
}

__device__ __forceinline__ void mma_bf16(float* c, uint32_t a0, uint32_t a1,
                                         uint32_t a2, uint32_t a3,
                                         uint32_t b0, uint32_t b1) {
    asm volatile(
        "mma.sync.aligned.m16n8k16.row.col.f32.bf16.bf16.f32 "
        "{%0,%1,%2,%3}, {%4,%5,%6,%7}, {%8,%9}, {%0,%1,%2,%3};"
        : "+f"(c[0]), "+f"(c[1]), "+f"(c[2]), "+f"(c[3])
        : "r"(a0), "r"(a1), "r"(a2), "r"(a3), "r"(b0), "r"(b1));
}

__device__ __forceinline__ void ldsm_x4(uint32_t& r0, uint32_t& r1,
                                        uint32_t& r2, uint32_t& r3,
                                        uint32_t addr) {
    asm volatile("ldmatrix.sync.aligned.m8n8.x4.shared.b16 {%0,%1,%2,%3}, [%4];"
                 : "=r"(r0), "=r"(r1), "=r"(r2), "=r"(r3) : "r"(addr));
}

// precise split (round-to-nearest hi) - used in prep only
__device__ __forceinline__ void splitpack(float e0, float e1,
                                          uint32_t& hi, uint32_t& lo) {
    __nv_bfloat16 h0 = __float2bfloat16_rn(e0);
    __nv_bfloat16 h1 = __float2bfloat16_rn(e1);
    float h0f = __bfloat162float(h0);
    float h1f = __bfloat162float(h1);
    __nv_bfloat16 l0 = __float2bfloat16_rn(e0 - h0f);
    __nv_bfloat16 l1 = __float2bfloat16_rn(e1 - h1f);
    hi = ((uint32_t)__bfloat16_as_ushort(h1) << 16) | __bfloat16_as_ushort(h0);
    lo = ((uint32_t)__bfloat16_as_ushort(l1) << 16) | __bfloat16_as_ushort(l0);
}

// fast truncation split: hi = trunc16(e) exact, lo = trunc16(e - hi)
__device__ __forceinline__ void splitpack_fast(float e0, float e1,
                                               uint32_t& hi, uint32_t& lo) {
    uint32_t b0 = __float_as_uint(e0), b1 = __float_as_uint(e1);
    hi = __byte_perm(b0, b1, 0x7632);
    float l0f = e0 - __uint_as_float(b0 & 0xffff0000u);
    float l1f = e1 - __uint_as_float(b1 & 0xffff0000u);
    lo = __byte_perm(__float_as_uint(l0f), __float_as_uint(l1f), 0x7632);
}

// tanh-approx GELU with HW tanh (inputs here are small, |x| << 1)
__device__ __forceinline__ float gelu_fast(float x) {
    float u = x * fmaf(0.0356774081f, x * x, 0.7978845608f);
    float t;
    asm("tanh.approx.f32 %0, %1;" : "=f"(t) : "f"(u));
    return 0.5f * x * (1.0f + t);
}

// ---------------------------------------------------------------------------
__global__ void mask_kernel(const float* __restrict__ nf) {
    int bn = blockIdx.x;
    const float4* p = (const float4*)(nf + (size_t)bn * FD);
    int nz = 0;
    for (int q = threadIdx.x; q < FD / 4; q += blockDim.x) {
        float4 v = p[q];
        nz |= (v.x != 0.0f) | (v.y != 0.0f) | (v.z != 0.0f) | (v.w != 0.0f);
    }
    int any = __syncthreads_or(nz);
    if (threadIdx.x == 0) g_pad[bn] = (any == 0) ? 1 : 0;
}

// ---------------------------------------------------------------------------
// pack w1^T / w2^T into mma B-fragment order (precise rn split; runs once)
// ---------------------------------------------------------------------------
__global__ void prep_kernel(const float* __restrict__ w1,
                            const float* __restrict__ w2) {
    int t = blockIdx.x * 256 + threadIdx.x;     // grid 16 x 256 = 4096
    {
        int idx = t;
        int s  = idx >> 9;
        int nb = (idx >> 5) & 15;
        int l  = idx & 31;
        int h  = nb * 8 + (l >> 2);
        int kp = s * 8 + (l & 3);
        float v0 = w1[(2 * kp) * 128 + h];
        float v1 = w1[(2 * kp + 1) * 128 + h];
        float v2 = w1[(2 * (kp + 4)) * 128 + h];
        float v3 = w1[(2 * (kp + 4) + 1) * 128 + h];
        uint32_t h0, l0, h1, l1;
        splitpack(v0, v1, h0, l0);
        splitpack(v2, v3, h1, l1);
        g_B1hi[idx] = make_uint2(h0, h1);
        g_B1lo[idx] = make_uint2(l0, l1);
    }
    if (t < 1024) {
        int idx = t;
        int s  = idx >> 7;
        int nb = (idx >> 5) & 3;
        int l  = idx & 31;
        int m  = nb * 8 + (l >> 2);
        int hp = s * 8 + (l & 3);
        float v0 = w2[(2 * hp) * 32 + m];
        float v1 = w2[(2 * hp + 1) * 32 + m];
        float v2 = w2[(2 * (hp + 4)) * 32 + m];
        float v3 = w2[(2 * (hp + 4) + 1) * 32 + m];
        uint32_t h0, l0, h1, l1;
        splitpack(v0, v1, h0, l0);
        splitpack(v2, v3, h1, l1);
        g_B2hi[idx] = make_uint2(h0, h1);
        g_B2lo[idx] = make_uint2(l0, l1);
    }
}

// ---------------------------------------------------------------------------
// main: one block per (i, b, jquarter); 256 threads; occupancy 3
// ---------------------------------------------------------------------------
__global__ __launch_bounds__(256, 3)
void main_kernel(const float* __restrict__ pos,
                 const float* __restrict__ means,
                 const float* __restrict__ betas,
                 const float* __restrict__ b1,
                 const float* __restrict__ b2,
                 float* __restrict__ gab,
                 float* __restrict__ dpos)
{
    extern __shared__ char smem[];
    const uint32_t sbase = smem_u32(smem);
    uint32_t* Ahi  = (uint32_t*)(smem + AHIO);
    uint32_t* Alo  = (uint32_t*)(smem + ALOO);
    uint32_t* Ghi  = (uint32_t*)(smem + GHIO);
    uint32_t* Glo  = (uint32_t*)(smem + GLOO);
    float*    Cst  = (float*)(smem + CSTO);
    float*    ts   = (float*)(smem + TSOF);
    float*    keep = (float*)(smem + KEEPO);
    float2*   spart = (float2*)(smem + SPARTO);

    const int i    = blockIdx.x;
    const int b    = blockIdx.y;
    const int jq   = blockIdx.z;        // j-quarter: rows jq*64 .. jq*64+63
    const int tid  = threadIdx.x;
    const int w    = tid >> 5;          // 0..7
    const int lane = tid & 31;
    const int g    = lane >> 2;
    const int c4   = lane & 3;

    // ldmatrix per-lane address components (A / G operand pattern)
    const int lmat = lane >> 3, lrow = lane & 7;
    const int rowA = lrow + 8 * (lmat & 1);
    const int kaddA = (lmat >> 1) * 4;

    // ---- phase 0: dpos, t[jl], keep[jl] for this quarter's 64 rows ----
    const float pix = pos[(b * NN + i) * 3 + 0];
    const float piy = pos[(b * NN + i) * 3 + 1];
    const float piz = pos[(b * NN + i) * 3 + 2];
    if (tid < 64) {
        int jl = tid;
        int j  = jq * 64 + jl;
        float pjx = pos[(b * NN + j) * 3 + 0];
        float pjy = pos[(b * NN + j) * 3 + 1];
        float pjz = pos[(b * NN + j) * 3 + 2];
        float dx = pix - pjx, dy = piy - pjy, dz = piz - pjz;
        size_t dbase = (((size_t)(b * NN + i)) * NN + j) * 3;
        dpos[dbase + 0] = dx;
        dpos[dbase + 1] = dy;
        dpos[dbase + 2] = dz;
        float r = dx * dx + dy * dy + dz * dz;
        float d = (r > 0.0f) ? sqrtf(r) : 0.0f;
        ts[jl] = expf(-d);              // precise (beta-amplified sensitivity)
        keep[jl] = g_pad[b * NN + j] ? 0.0f : 1.0f;
    }
    __syncthreads();

    // ================= GEMM1: C1[64j x 128h] = ef @ w1 =====================
    const int wj = w & 1;    // 32 rows at wj*32
    const int wh = w >> 1;   // 32 cols at wh*32
    const int gkp = tid & 15;
    const int gjg = tid >> 4;           // 0..15, 4 j rows each

    float acc[2][4][4];
#pragma unroll
    for (int mi = 0; mi < 2; mi++)
#pragma unroll
        for (int ni = 0; ni < 4; ni++)
#pragma unroll
            for (int q = 0; q < 4; q++) acc[mi][ni][q] = 0.0f;

    for (int kc = 0; kc < 4; kc++) {
        // ---- generate A chunk [64 j][32 k] + masked partial sums ----
        {
            int k0 = kc * 32 + 2 * gkp;
            float mk0 = means[k0], mk1 = means[k0 + 1];
            float bk0 = betas[k0], bk1 = betas[k0 + 1];
            float s0 = 0.0f, s1 = 0.0f;
#pragma unroll
            for (int q = 0; q < 4; q++) {
                int jl = gjg * 4 + q;
                float t  = ts[jl];
                float kj = keep[jl];
                float d0 = t - mk0, d1 = t - mk1;
                float e0 = __expf(-bk0 * d0 * d0);
                float e1 = __expf(-bk1 * d1 * d1);
                s0 += e0 * kj;  s1 += e1 * kj;
                uint32_t hi, lo;
                splitpack_fast(e0, e1, hi, lo);
                Ahi[jl * 20 + gkp] = hi;
                Alo[jl * 20 + gkp] = lo;
            }
            spart[tid] = make_float2(s0, s1);
        }
        __syncthreads();

        // ---- fold this quarter's masked j-sums (warp 0; overlaps MMA) ----
        if (tid < 32) {
            int kp = tid >> 1, c = tid & 1;
            float s = 0.0f;
#pragma unroll
            for (int jg = 0; jg < 16; jg++) {
                float2 v = spart[jg * 16 + kp];
                s += c ? v.y : v.x;
            }
            g_sumef4[(size_t)jq * (BB * NN * KK)
                     + ((size_t)(b * NN + i)) * 128 + kc * 32 + tid] = s;
        }

        // ---- MMA: 2 k-steps of 16; B frags streamed from L2 ----
#pragma unroll
        for (int ks = 0; ks < 2; ks++) {
            int s = kc * 2 + ks;
            uint2 bh[4], bl[4];
#pragma unroll
            for (int ni = 0; ni < 4; ni++) {
                int idx = ((s * 16 + wh * 4 + ni) * 32) + lane;
                bh[ni] = g_B1hi[idx];
                bl[ni] = g_B1lo[idx];
            }
            int kloc = ks * 8;
#pragma unroll
            for (int mi = 0; mi < 2; mi++) {
                uint32_t aoff = (uint32_t)(((wj * 32 + mi * 16 + rowA) * 20
                                            + kloc + kaddA) * 4);
                uint32_t ah0, ah1, ah2, ah3, al0, al1, al2, al3;
                ldsm_x4(ah0, ah1, ah2, ah3, sbase + AHIO + aoff);
                ldsm_x4(al0, al1, al2, al3, sbase + ALOO + aoff);
#pragma unroll
                for (int ni = 0; ni < 4; ni++) {
                    mma_bf16(acc[mi][ni], ah0, ah1, ah2, ah3, bh[ni].x, bh[ni].y);
                    mma_bf16(acc[mi][ni], al0, al1, al2, al3, bh[ni].x, bh[ni].y);
                    mma_bf16(acc[mi][ni], ah0, ah1, ah2, ah3, bl[ni].x, bl[ni].y);
                }
            }
        }
        __syncthreads();   // A consumed; next gen may overwrite
    }

    // ---- epilogue1: +b1, fast GELU, split/pack into G (aliases A) ----
    {
        float b1r0[4], b1r1[4];
#pragma unroll
        for (int ni = 0; ni < 4; ni++) {
            int h0 = wh * 32 + ni * 8 + c4 * 2;
            b1r0[ni] = b1[h0];
            b1r1[ni] = b1[h0 + 1];
        }
#pragma unroll
        for (int mi = 0; mi < 2; mi++) {
            int r0 = wj * 32 + mi * 16 + g;
            int r1 = r0 + 8;
#pragma unroll
            for (int ni = 0; ni < 4; ni++) {
                int hp = wh * 16 + ni * 4 + c4;
                float g00 = gelu_fast(acc[mi][ni][0] + b1r0[ni]);
                float g01 = gelu_fast(acc[mi][ni][1] + b1r1[ni]);
                float g10 = gelu_fast(acc[mi][ni][2] + b1r0[ni]);
                float g11 = gelu_fast(acc[mi][ni][3] + b1r1[ni]);
                uint32_t hi, lo;
                splitpack_fast(g00, g01, hi, lo);
                Ghi[r0 * 68 + hp] = hi;  Glo[r0 * 68 + hp] = lo;
                splitpack_fast(g10, g11, hi, lo);
                Ghi[r1 * 68 + hp] = hi;  Glo[r1 * 68 + hp] = lo;
            }
        }
    }
    __syncthreads();

    // ================= GEMM2: C2[64j x 32m] = G @ w2 =======================
    // 8 warps: 16j x 16m each. jt = (w>>1)*16, m-halves by (w&1)
    float acc2[2][4];
#pragma unroll
    for (int ni = 0; ni < 2; ni++)
#pragma unroll
        for (int q = 0; q < 4; q++) acc2[ni][q] = 0.0f;

    const int jt = (w >> 1) * 16;
    const int mh = w & 1;               // m-half: cols mh*16
#pragma unroll
    for (int s = 0; s < 8; s++) {
        uint32_t goff = (uint32_t)(((jt + rowA) * 68 + s * 8 + kaddA) * 4);
        uint32_t gh0, gh1, gh2, gh3, gl0, gl1, gl2, gl3;
        ldsm_x4(gh0, gh1, gh2, gh3, sbase + GHIO + goff);
        ldsm_x4(gl0, gl1, gl2, gl3, sbase + GLOO + goff);
        uint2 bh[2], bl[2];
#pragma unroll
        for (int ni = 0; ni < 2; ni++) {
            int idx = ((s * 4 + mh * 2 + ni) * 32) + lane;
            bh[ni] = g_B2hi[idx];
            bl[ni] = g_B2lo[idx];
        }
#pragma unroll
        for (int ni = 0; ni < 2; ni++) {
            mma_bf16(acc2[ni], gh0, gh1, gh2, gh3, bh[ni].x, bh[ni].y);
            mma_bf16(acc2[ni], gl0, gl1, gl2, gl3, bh[ni].x, bh[ni].y);
            mma_bf16(acc2[ni], gh0, gh1, gh2, gh3, bl[ni].x, bl[ni].y);
        }
    }
    __syncthreads();   // G consumed; Cst may alias

    // ---- epilogue2: +b2 into staging ----
#pragma unroll
    for (int ni = 0; ni < 2; ni++) {
        int m0 = mh * 16 + ni * 8 + c4 * 2;
        float e0 = b2[m0], e1 = b2[m0 + 1];
        int r0 = jt + g, r1 = r0 + 8;
        Cst[r0 * 37 + m0]     = acc2[ni][0] + e0;
        Cst[r0 * 37 + m0 + 1] = acc2[ni][1] + e1;
        Cst[r1 * 37 + m0]     = acc2[ni][2] + e0;
        Cst[r1 * 37 + m0 + 1] = acc2[ni][3] + e1;
    }
    __syncthreads();

    // ---- coalesced gab stores: gab[b][m][i][jq*64 + jl] ----
    {
#pragma unroll
        for (int it = 0; it < 8; it++) {
            int idx = it * 256 + tid;
            int m  = idx >> 6;
            int jl = idx & 63;
            int j  = jq * 64 + jl;
            float v = Cst[jl * 37 + m];
            gab[(((size_t)(b * HH + m)) * NN + i) * NN + j] =
                (keep[jl] == 0.0f) ? -1e20f : v;
        }
    }
}

// ---------------------------------------------------------------------------
// merge_edge_features = (sum over 4 quarters) @ ew + eb
// grid (256 row-tiles of 8, 3 col-chunks); thread: 1 col x 8 rows; float4 sef
// ---------------------------------------------------------------------------
__global__ __launch_bounds__(256)
void merge_kernel(const float* __restrict__ ew,
                  const float* __restrict__ eb,
                  float* __restrict__ out)
{
    __shared__ float sef[8 * 128];
    const int r0  = blockIdx.x * 8;
    const int col = blockIdx.y * 256 + threadIdx.x;
    const int tid = threadIdx.x;

#pragma unroll
    for (int q = 0; q < 4; q++) {
        size_t off = (size_t)r0 * 128 + tid + 256 * q;
        float s = g_sumef4[off]
                + g_sumef4[(size_t)(BB*NN*KK) + off]
                + g_sumef4[(size_t)(2*BB*NN*KK) + off]
                + g_sumef4[(size_t)(3*BB*NN*KK) + off];
        sef[tid + 256 * q] = s;
    }
    __syncthreads();

    float acc[8];
    {
        float e = eb[col];
#pragma unroll
        for (int r = 0; r < 8; r++) acc[r] = e;
    }

    const float4* sef4 = (const float4*)sef;
#pragma unroll 2
    for (int k4 = 0; k4 < 32; k4++) {
        int k = k4 * 4;
        float v0 = ew[(size_t)(k + 0) * EMB + col];
        float v1 = ew[(size_t)(k + 1) * EMB + col];
        float v2 = ew[(size_t)(k + 2) * EMB + col];
        float v3 = ew[(size_t)(k + 3) * EMB + col];
#pragma unroll
        for (int r = 0; r < 8; r++) {
            float4 s = sef4[r * 32 + k4];
            acc[r] = fmaf(s.x, v0, acc[r]);
            acc[r] = fmaf(s.y, v1, acc[r]);
            acc[r] = fmaf(s.z, v2, acc[r]);
            acc[r] = fmaf(s.w, v3, acc[r]);
        }
    }

#pragma unroll
    for (int r = 0; r < 8; r++)
        out[(size_t)(r0 + r) * EMB + col] = acc[r];
}

// ---------------------------------------------------------------------------
extern "C" void kernel_launch(void* const* d_in, const int* in_sizes, int n_in,
                              void* d_out, int out_size) {
    const float* nf    = (const float*)d_in[0];
    const float* pos   = (const float*)d_in[1];
    const float* means = (const float*)d_in[2];
    const float* betas = (const float*)d_in[3];
    const float* w1    = (const float*)d_in[4];
    const float* b1    = (const float*)d_in[5];
    const float* w2    = (const float*)d_in[6];
    const float* b2    = (const float*)d_in[7];
    const float* ew    = (const float*)d_in[8];
    const float* eb    = (const float*)d_in[9];

    float* out  = (float*)d_out;
    float* gab  = out;
    float* mef  = out + GAB_ELEMS;
    float* dpos = out + GAB_ELEMS + MEF_ELEMS;

    cudaFuncSetAttribute(main_kernel,
                         cudaFuncAttributeMaxDynamicSharedMemorySize,
                         SMEM_TOTAL);

    prep_kernel<<<16, 256>>>(w1, w2);
    mask_kernel<<<BB * NN, 128>>>(nf);

    dim3 grid(NN, BB, 4);
    main_kernel<<<grid, 256, SMEM_TOTAL>>>(
        pos, means, betas, b1, b2, gab, dpos);

    dim3 mgrid((BB * NN) / 8, 3);
    merge_kernel<<<mgrid, 256>>>(ew, eb, mef);
}

// round 15
// speedup vs baseline: 1.7142x; 1.7142x over previous
#include <cuda_runtime.h>
#include <cuda_bf16.h>
#include <math.h>
#include <stdint.h>

#define BB 8
#define NN 256
#define KK 128
#define HH 32
#define EMB 768
#define FD 768

#define GAB_ELEMS   (BB*HH*NN*NN)      // 16777216
#define MEF_ELEMS   (BB*NN*EMB)        // 1572864

// scratch (no cudaMalloc allowed)
__device__ float g_sumef2[2 * BB * NN * KK];   // [jh][b*N+i][k]
__device__ int   g_pad[BB * NN];
// pre-packed mma B-fragments (bf16 hi/lo pairs), exact lane order
__device__ uint2 g_B1hi[4096], g_B1lo[4096];   // [(s*16+nb)*32 + lane]
__device__ uint2 g_B2hi[1024], g_B2lo[1024];   // [(s*4+nb)*32 + lane]

// ---------------------------------------------------------------------------
// SMEM layout (bytes), 256-thread block, 128 j rows:
//   A[2] : ef chunk bf16-pairs [128 j][20] (16 kpairs + 4 pad) hi/lo, x2 buf
//          -> 40960 B, entirely inside the G region (dead before G written)
//   G    : gelu bf16-pairs    [128 j][68] (64 hpairs + 4 pad) hi/lo
//   CST  : C2 staging fp32    [128 j][37] (over G-hi, after GEMM2)
// all alias windows fenced by __syncthreads
// ---------------------------------------------------------------------------
#define AHI0   0         // 10240
#define ALO0   10240     // -> 20480
#define AHI1   20480     // 10240
#define ALO1   30720     // -> 40960 (inside G: 0..69632)
#define GHIO   0         // 34816
#define GLOO   34816     // 34816 -> 69632
#define CSTO   0         // 18944 (over G-hi, after GEMM2)
#define TSOF   69632     // 512
#define KEEPO  70144     // 512
#define SPARTO 70656     // 2 x 2048 (2 x 256 x float2)
#define SMEM_TOTAL 74752

// ---------------------------------------------------------------------------
__device__ __forceinline__ uint32_t smem_u32(const void* p) {
    uint32_t a;
    asm("{ .reg .u64 t; cvta.to.shared.u64 t, %1; cvt.u32.u64 %0, t; }"
        : "=r"(a) : "l"(p));
    return a;
}

__device__ __forceinline__ void mma_bf16(float* c, uint32_t a0, uint32_t a1,
                                         uint32_t a2, uint32_t a3,
                                         uint32_t b0, uint32_t b1) {
    asm volatile(
        "mma.sync.aligned.m16n8k16.row.col.f32.bf16.bf16.f32 "
        "{%0,%1,%2,%3}, {%4,%5,%6,%7}, {%8,%9}, {%0,%1,%2,%3};"
        : "+f"(c[0]), "+f"(c[1]), "+f"(c[2]), "+f"(c[3])
        : "r"(a0), "r"(a1), "r"(a2), "r"(a3), "r"(b0), "r"(b1));
}

__device__ __forceinline__ void ldsm_x4(uint32_t& r0, uint32_t& r1,
                                        uint32_t& r2, uint32_t& r3,
                                        uint32_t addr) {
    asm volatile("ldmatrix.sync.aligned.m8n8.x4.shared.b16 {%0,%1,%2,%3}, [%4];"
                 : "=r"(r0), "=r"(r1), "=r"(r2), "=r"(r3) : "r"(addr));
}

__device__ __forceinline__ float ex2_fast(float x) {
    float r;
    asm("ex2.approx.ftz.f32 %0, %1;" : "=f"(r) : "f"(x));
    return r;
}

// precise split (round-to-nearest hi) - used in prep only
__device__ __forceinline__ void splitpack(float e0, float e1,
                                          uint32_t& hi, uint32_t& lo) {
    __nv_bfloat16 h0 = __float2bfloat16_rn(e0);
    __nv_bfloat16 h1 = __float2bfloat16_rn(e1);
    float h0f = __bfloat162float(h0);
    float h1f = __bfloat162float(h1);
    __nv_bfloat16 l0 = __float2bfloat16_rn(e0 - h0f);
    __nv_bfloat16 l1 = __float2bfloat16_rn(e1 - h1f);
    hi = ((uint32_t)__bfloat16_as_ushort(h1) << 16) | __bfloat16_as_ushort(h0);
    lo = ((uint32_t)__bfloat16_as_ushort(l1) << 16) | __bfloat16_as_ushort(l0);
}

// fast truncation split: hi = trunc16(e) exact, lo = trunc16(e - hi)
__device__ __forceinline__ void splitpack_fast(float e0, float e1,
                                               uint32_t& hi, uint32_t& lo) {
    uint32_t b0 = __float_as_uint(e0), b1 = __float_as_uint(e1);
    hi = __byte_perm(b0, b1, 0x7632);
    float l0f = e0 - __uint_as_float(b0 & 0xffff0000u);
    float l1f = e1 - __uint_as_float(b1 & 0xffff0000u);
    lo = __byte_perm(__float_as_uint(l0f), __float_as_uint(l1f), 0x7632);
}

// tanh-approx GELU with HW tanh (inputs here are small, |x| << 1)
__device__ __forceinline__ float gelu_fast(float x) {
    float u = x * fmaf(0.0356774081f, x * x, 0.7978845608f);
    float t;
    asm("tanh.approx.f32 %0, %1;" : "=f"(t) : "f"(u));
    return 0.5f * x * (1.0f + t);
}

// ---------------------------------------------------------------------------
__global__ void mask_kernel(const float* __restrict__ nf) {
    int bn = blockIdx.x;
    const float4* p = (const float4*)(nf + (size_t)bn * FD);
    int nz = 0;
    for (int q = threadIdx.x; q < FD / 4; q += blockDim.x) {
        float4 v = p[q];
        nz |= (v.x != 0.0f) | (v.y != 0.0f) | (v.z != 0.0f) | (v.w != 0.0f);
    }
    int any = __syncthreads_or(nz);
    if (threadIdx.x == 0) g_pad[bn] = (any == 0) ? 1 : 0;
}

// ---------------------------------------------------------------------------
// pack w1^T / w2^T into mma B-fragment order (precise rn split; runs once)
// ---------------------------------------------------------------------------
__global__ void prep_kernel(const float* __restrict__ w1,
                            const float* __restrict__ w2) {
    int t = blockIdx.x * 256 + threadIdx.x;     // grid 16 x 256 = 4096
    {
        int idx = t;
        int s  = idx >> 9;
        int nb = (idx >> 5) & 15;
        int l  = idx & 31;
        int h  = nb * 8 + (l >> 2);
        int kp = s * 8 + (l & 3);
        float v0 = w1[(2 * kp) * 128 + h];
        float v1 = w1[(2 * kp + 1) * 128 + h];
        float v2 = w1[(2 * (kp + 4)) * 128 + h];
        float v3 = w1[(2 * (kp + 4) + 1) * 128 + h];
        uint32_t h0, l0, h1, l1;
        splitpack(v0, v1, h0, l0);
        splitpack(v2, v3, h1, l1);
        g_B1hi[idx] = make_uint2(h0, h1);
        g_B1lo[idx] = make_uint2(l0, l1);
    }
    if (t < 1024) {
        int idx = t;
        int s  = idx >> 7;
        int nb = (idx >> 5) & 3;
        int l  = idx & 31;
        int m  = nb * 8 + (l >> 2);
        int hp = s * 8 + (l & 3);
        float v0 = w2[(2 * hp) * 32 + m];
        float v1 = w2[(2 * hp + 1) * 32 + m];
        float v2 = w2[(2 * (hp + 4)) * 32 + m];
        float v3 = w2[(2 * (hp + 4) + 1) * 32 + m];
        uint32_t h0, l0, h1, l1;
        splitpack(v0, v1, h0, l0);
        splitpack(v2, v3, h1, l1);
        g_B2hi[idx] = make_uint2(h0, h1);
        g_B2lo[idx] = make_uint2(l0, l1);
    }
}

// ---------------------------------------------------------------------------
// main: one block per (i, b, jhalf); 256 threads; occupancy 2
// ---------------------------------------------------------------------------
__global__ __launch_bounds__(256, 2)
void main_kernel(const float* __restrict__ pos,
                 const float* __restrict__ means,
                 const float* __restrict__ betas,
                 const float* __restrict__ b1,
                 const float* __restrict__ b2,
                 float* __restrict__ gab,
                 float* __restrict__ dpos)
{
    extern __shared__ char smem[];
    const uint32_t sbase = smem_u32(smem);
    uint32_t* Ghi  = (uint32_t*)(smem + GHIO);
    uint32_t* Glo  = (uint32_t*)(smem + GLOO);
    float*    Cst  = (float*)(smem + CSTO);
    float*    ts   = (float*)(smem + TSOF);
    float*    keep = (float*)(smem + KEEPO);
    float2*   spart = (float2*)(smem + SPARTO);  // [2][256]

    const int i    = blockIdx.x;
    const int b    = blockIdx.y;
    const int jh   = blockIdx.z;
    const int tid  = threadIdx.x;
    const int w    = tid >> 5;          // 0..7
    const int lane = tid & 31;
    const int g    = lane >> 2;
    const int c4   = lane & 3;

    // ldmatrix per-lane address components (A / G operand pattern)
    const int lmat = lane >> 3, lrow = lane & 7;
    const int rowA = lrow + 8 * (lmat & 1);
    const int kaddA = (lmat >> 1) * 4;

    // ---- phase 0: dpos, t[jl], keep[jl] for this half's 128 rows ----
    const float pix = pos[(b * NN + i) * 3 + 0];
    const float piy = pos[(b * NN + i) * 3 + 1];
    const float piz = pos[(b * NN + i) * 3 + 2];
    if (tid < 128) {
        int jl = tid;
        int j  = jh * 128 + jl;
        float pjx = pos[(b * NN + j) * 3 + 0];
        float pjy = pos[(b * NN + j) * 3 + 1];
        float pjz = pos[(b * NN + j) * 3 + 2];
        float dx = pix - pjx, dy = piy - pjy, dz = piz - pjz;
        size_t dbase = (((size_t)(b * NN + i)) * NN + j) * 3;
        dpos[dbase + 0] = dx;
        dpos[dbase + 1] = dy;
        dpos[dbase + 2] = dz;
        float r = dx * dx + dy * dy + dz * dz;
        float d = (r > 0.0f) ? sqrtf(r) : 0.0f;
        ts[jl] = expf(-d);              // precise (beta-amplified sensitivity)
        keep[jl] = g_pad[b * NN + j] ? 0.0f : 1.0f;
    }
    __syncthreads();

    // ================= GEMM1: C1[128j x 128h] = ef @ w1 ====================
    const int wj = w & 1;    // 64 rows at wj*64
    const int wh = w >> 1;   // 32 cols at wh*32
    const int gkp = tid & 15;
    const int gjg = tid >> 4;           // 0..15, 8 j each

    float acc[4][4][4];
#pragma unroll
    for (int mi = 0; mi < 4; mi++)
#pragma unroll
        for (int ni = 0; ni < 4; ni++)
#pragma unroll
            for (int q = 0; q < 4; q++) acc[mi][ni][q] = 0.0f;

    // ---- generate chunk 0 into buffer 0 ----
    {
        uint32_t* Ah = (uint32_t*)(smem + AHI0);
        uint32_t* Al = (uint32_t*)(smem + ALO0);
        int k0 = 2 * gkp;
        float nb0 = -betas[k0]     * 1.44269504088896f;
        float nb1 = -betas[k0 + 1] * 1.44269504088896f;
        float mk0 = means[k0], mk1 = means[k0 + 1];
        float s0 = 0.0f, s1 = 0.0f;
#pragma unroll
        for (int q = 0; q < 8; q++) {
            int jl = gjg * 8 + q;
            float t  = ts[jl];
            float kj = keep[jl];
            float d0 = t - mk0, d1 = t - mk1;
            float e0 = ex2_fast(nb0 * d0 * d0);
            float e1 = ex2_fast(nb1 * d1 * d1);
            s0 += e0 * kj;  s1 += e1 * kj;
            uint32_t hi, lo;
            splitpack_fast(e0, e1, hi, lo);
            Ah[jl * 20 + gkp] = hi;
            Al[jl * 20 + gkp] = lo;
        }
        spart[tid] = make_float2(s0, s1);
    }
    __syncthreads();

    // ============ pipelined K-chunk loop (4 chunks of 32 k) ================
    for (int kc = 0; kc < 4; kc++) {
        const int buf = kc & 1;
        const uint32_t uAhi = sbase + (buf ? AHI1 : AHI0);
        const uint32_t uAlo = uAhi + 10240;

        // ---- fold this half's masked j-sums of chunk kc (warp 0) ----
        if (tid < 32) {
            int kp = tid >> 1, c = tid & 1;
            const float2* sp = spart + buf * 256;
            float s = 0.0f;
#pragma unroll
            for (int jg = 0; jg < 16; jg++) {
                float2 v = sp[jg * 16 + kp];
                s += c ? v.y : v.x;
            }
            g_sumef2[(size_t)jh * (BB * NN * KK)
                     + ((size_t)(b * NN + i)) * 128 + kc * 32 + tid] = s;
        }

        // ---- MMA: 2 k-steps of 16; B frags streamed from L2 ----
#pragma unroll
        for (int ks = 0; ks < 2; ks++) {
            int s = kc * 2 + ks;
            uint2 bh[4], bl[4];
#pragma unroll
            for (int ni = 0; ni < 4; ni++) {
                int idx = ((s * 16 + wh * 4 + ni) * 32) + lane;
                bh[ni] = g_B1hi[idx];
                bl[ni] = g_B1lo[idx];
            }
            int kloc = ks * 8;
#pragma unroll
            for (int mi = 0; mi < 4; mi++) {
                uint32_t aoff = (uint32_t)(((wj * 64 + mi * 16 + rowA) * 20
                                            + kloc + kaddA) * 4);
                uint32_t ah0, ah1, ah2, ah3, al0, al1, al2, al3;
                ldsm_x4(ah0, ah1, ah2, ah3, uAhi + aoff);
                ldsm_x4(al0, al1, al2, al3, uAlo + aoff);
#pragma unroll
                for (int ni = 0; ni < 4; ni++) {
                    mma_bf16(acc[mi][ni], ah0, ah1, ah2, ah3, bh[ni].x, bh[ni].y);
                    mma_bf16(acc[mi][ni], al0, al1, al2, al3, bh[ni].x, bh[ni].y);
                    mma_bf16(acc[mi][ni], ah0, ah1, ah2, ah3, bl[ni].x, bl[ni].y);
                }
            }
        }

        // ---- generate chunk kc+1 into other buffer (overlaps HMMA drain) --
        if (kc < 3) {
            uint32_t* Ah = (uint32_t*)(smem + ((buf ^ 1) ? AHI1 : AHI0));
            uint32_t* Al = (uint32_t*)(smem + ((buf ^ 1) ? ALO1 : ALO0));
            int k0 = (kc + 1) * 32 + 2 * gkp;
            float nb0 = -betas[k0]     * 1.44269504088896f;
            float nb1 = -betas[k0 + 1] * 1.44269504088896f;
            float mk0 = means[k0], mk1 = means[k0 + 1];
            float s0 = 0.0f, s1 = 0.0f;
#pragma unroll
            for (int q = 0; q < 8; q++) {
                int jl = gjg * 8 + q;
                float t  = ts[jl];
                float kj = keep[jl];
                float d0 = t - mk0, d1 = t - mk1;
                float e0 = ex2_fast(nb0 * d0 * d0);
                float e1 = ex2_fast(nb1 * d1 * d1);
                s0 += e0 * kj;  s1 += e1 * kj;
                uint32_t hi, lo;
                splitpack_fast(e0, e1, hi, lo);
                Ah[jl * 20 + gkp] = hi;
                Al[jl * 20 + gkp] = lo;
            }
            spart[(buf ^ 1) * 256 + tid] = make_float2(s0, s1);
        }
        __syncthreads();   // gen(kc+1) visible; ldsm(kc) done before reuse
    }

    // ---- epilogue1: +b1, fast GELU, split/pack into G (aliases A) ----
    {
        float b1r0[4], b1r1[4];
#pragma unroll
        for (int ni = 0; ni < 4; ni++) {
            int h0 = wh * 32 + ni * 8 + c4 * 2;
            b1r0[ni] = b1[h0];
            b1r1[ni] = b1[h0 + 1];
        }
#pragma unroll
        for (int mi = 0; mi < 4; mi++) {
            int r0 = wj * 64 + mi * 16 + g;
            int r1 = r0 + 8;
#pragma unroll
            for (int ni = 0; ni < 4; ni++) {
                int hp = wh * 16 + ni * 4 + c4;
                float g00 = gelu_fast(acc[mi][ni][0] + b1r0[ni]);
                float g01 = gelu_fast(acc[mi][ni][1] + b1r1[ni]);
                float g10 = gelu_fast(acc[mi][ni][2] + b1r0[ni]);
                float g11 = gelu_fast(acc[mi][ni][3] + b1r1[ni]);
                uint32_t hi, lo;
                splitpack_fast(g00, g01, hi, lo);
                Ghi[r0 * 68 + hp] = hi;  Glo[r0 * 68 + hp] = lo;
                splitpack_fast(g10, g11, hi, lo);
                Ghi[r1 * 68 + hp] = hi;  Glo[r1 * 68 + hp] = lo;
            }
        }
    }
    __syncthreads();

    // ================= GEMM2: C2[128j x 32m] = G @ w2 ======================
    float acc2[4][4];
#pragma unroll
    for (int ni = 0; ni < 4; ni++)
#pragma unroll
        for (int q = 0; q < 4; q++) acc2[ni][q] = 0.0f;

    const int jt = w * 16;
#pragma unroll
    for (int s = 0; s < 8; s++) {
        uint32_t goff = (uint32_t)(((jt + rowA) * 68 + s * 8 + kaddA) * 4);
        uint32_t gh0, gh1, gh2, gh3, gl0, gl1, gl2, gl3;
        ldsm_x4(gh0, gh1, gh2, gh3, sbase + GHIO + goff);
        ldsm_x4(gl0, gl1, gl2, gl3, sbase + GLOO + goff);
        uint2 bh[4], bl[4];
#pragma unroll
        for (int ni = 0; ni < 4; ni++) {
            int idx = ((s * 4 + ni) * 32) + lane;
            bh[ni] = g_B2hi[idx];
            bl[ni] = g_B2lo[idx];
        }
#pragma unroll
        for (int ni = 0; ni < 4; ni++) {
            mma_bf16(acc2[ni], gh0, gh1, gh2, gh3, bh[ni].x, bh[ni].y);
            mma_bf16(acc2[ni], gl0, gl1, gl2, gl3, bh[ni].x, bh[ni].y);
            mma_bf16(acc2[ni], gh0, gh1, gh2, gh3, bl[ni].x, bl[ni].y);
        }
    }
    __syncthreads();   // G consumed; Cst may alias

    // ---- epilogue2: +b2 into staging ----
#pragma unroll
    for (int ni = 0; ni < 4; ni++) {
        int m0 = ni * 8 + c4 * 2;
        float e0 = b2[m0], e1 = b2[m0 + 1];
        int r0 = jt + g, r1 = r0 + 8;
        Cst[r0 * 37 + m0]     = acc2[ni][0] + e0;
        Cst[r0 * 37 + m0 + 1] = acc2[ni][1] + e1;
        Cst[r1 * 37 + m0]     = acc2[ni][2] + e0;
        Cst[r1 * 37 + m0 + 1] = acc2[ni][3] + e1;
    }
    __syncthreads();

    // ---- coalesced gab stores: gab[b][m][i][jh*128 + jl] ----
    {
#pragma unroll
        for (int it = 0; it < 16; it++) {
            int idx = it * 256 + tid;
            int m  = idx >> 7;
            int jl = idx & 127;
            int j  = jh * 128 + jl;
            float v = Cst[jl * 37 + m];
            gab[(((size_t)(b * HH + m)) * NN + i) * NN + j] =
                (keep[jl] == 0.0f) ? -1e20f : v;
        }
    }
}

// ---------------------------------------------------------------------------
// merge_edge_features = (sum over both halves) @ ew + eb
// grid (128 row-tiles, 3 col-chunks); thread: 1 col x 16 rows; float4 sef
// ---------------------------------------------------------------------------
__global__ __launch_bounds__(256)
void merge_kernel(const float* __restrict__ ew,
                  const float* __restrict__ eb,
                  float* __restrict__ out)
{
    __shared__ float sef[16 * 128];
    const int r0  = blockIdx.x * 16;
    const int col = blockIdx.y * 256 + threadIdx.x;
    const int tid = threadIdx.x;

#pragma unroll
    for (int q = 0; q < 8; q++) {
        size_t off = (size_t)r0 * 128 + tid + 256 * q;
        sef[tid + 256 * q] = g_sumef2[off] + g_sumef2[(size_t)(BB*NN*KK) + off];
    }
    __syncthreads();

    float acc[16];
    {
        float e = eb[col];
#pragma unroll
        for (int r = 0; r < 16; r++) acc[r] = e;
    }

    const float4* sef4 = (const float4*)sef;
#pragma unroll 2
    for (int k4 = 0; k4 < 32; k4++) {
        int k = k4 * 4;
        float v0 = ew[(size_t)(k + 0) * EMB + col];
        float v1 = ew[(size_t)(k + 1) * EMB + col];
        float v2 = ew[(size_t)(k + 2) * EMB + col];
        float v3 = ew[(size_t)(k + 3) * EMB + col];
#pragma unroll
        for (int r = 0; r < 16; r++) {
            float4 s = sef4[r * 32 + k4];
            acc[r] = fmaf(s.x, v0, acc[r]);
            acc[r] = fmaf(s.y, v1, acc[r]);
            acc[r] = fmaf(s.z, v2, acc[r]);
            acc[r] = fmaf(s.w, v3, acc[r]);
        }
    }

#pragma unroll
    for (int r = 0; r < 16; r++)
        out[(size_t)(r0 + r) * EMB + col] = acc[r];
}

// ---------------------------------------------------------------------------
extern "C" void kernel_launch(void* const* d_in, const int* in_sizes, int n_in,
                              void* d_out, int out_size) {
    const float* nf    = (const float*)d_in[0];
    const float* pos   = (const float*)d_in[1];
    const float* means = (const float*)d_in[2];
    const float* betas = (const float*)d_in[3];
    const float* w1    = (const float*)d_in[4];
    const float* b1    = (const float*)d_in[5];
    const float* w2    = (const float*)d_in[6];
    const float* b2    = (const float*)d_in[7];
    const float* ew    = (const float*)d_in[8];
    const float* eb    = (const float*)d_in[9];

    float* out  = (float*)d_out;
    float* gab  = out;
    float* mef  = out + GAB_ELEMS;
    float* dpos = out + GAB_ELEMS + MEF_ELEMS;

    cudaFuncSetAttribute(main_kernel,
                         cudaFuncAttributeMaxDynamicSharedMemorySize,
                         SMEM_TOTAL);

    prep_kernel<<<16, 256>>>(w1, w2);
    mask_kernel<<<BB * NN, 128>>>(nf);

    dim3 grid(NN, BB, 2);
    main_kernel<<<grid, 256, SMEM_TOTAL>>>(
        pos, means, betas, b1, b2, gab, dpos);

    dim3 mgrid((BB * NN) / 16, 3);
    merge_kernel<<<mgrid, 256>>>(ew, eb, mef);
}

// round 16
// speedup vs baseline: 2.3595x; 1.3765x over previous
#include <cuda_runtime.h>
#include <cuda_bf16.h>
#include <math.h>
#include <stdint.h>

#define BB 8
#define NN 256
#define KK 128
#define HH 32
#define EMB 768
#define FD 768

#define GAB_ELEMS   (BB*HH*NN*NN)      // 16777216
#define MEF_ELEMS   (BB*NN*EMB)        // 1572864

#define NT   32      // number of 8-row tiles per dimension
#define NPAIR 528    // NT*(NT+1)/2

// scratch (no cudaMalloc allowed)
__device__ float g_parts[(size_t)BB * NT * NT * 8 * KK];  // [b][ta][tb][ii][k]
__device__ int   g_pad[BB * NN];
// pre-packed mma B-fragments (bf16 hi/lo pairs), exact lane order
__device__ uint2 g_B1hi[4096], g_B1lo[4096];   // [(s*16+nb)*32 + lane]
__device__ uint2 g_B2hi[1024], g_B2lo[1024];   // [(s*4+nb)*32 + lane]

// ---------------------------------------------------------------------------
// SMEM layout (bytes), 256-thread block, 128 rows = 2 pair-tiles of 8x8 pairs
//   A[2]  : ef chunk bf16-pairs [128 r][20] hi/lo, double buffered (0..40960)
//   spB[2]: B-reduction dump, [2 tiles][8 ii][8 jj][16 kp] float2 (16K each)
//   G     : gelu bf16-pairs [128 r][68] hi/lo (0..69632, after chunks)
//   CST   : C2 staging fp32 [128 r][37] (over G-hi, after GEMM2)
// alias windows fenced by __syncthreads
// ---------------------------------------------------------------------------
#define AHI0   0         // 10240
#define ALO0   10240     // -> 20480
#define AHI1   20480
#define ALO1   30720     // -> 40960
#define SPB0   40960     // 16384 -> 57344
#define SPB1   57344     // 16384 -> 73728
#define GHIO   0         // 34816
#define GLOO   34816     // -> 69632
#define CSTO   0         // 18944
#define TSOF   73728     // 512  t per row
#define KJOF   74240     // 512  keep_j per row
#define KIOF   74752     // 512  keep_i per row
#define IROF   75264     // 512  i per row (int)
#define JROF   75776     // 512  j per row (int)
#define SMEM_TOTAL 76288

// ---------------------------------------------------------------------------
__device__ __forceinline__ uint32_t smem_u32(const void* p) {
    uint32_t a;
    asm("{ .reg .u64 t; cvta.to.shared.u64 t, %1; cvt.u32.u64 %0, t; }"
        : "=r"(a) : "l"(p));
    return a;
}

__device__ __forceinline__ void mma_bf16(float* c, uint32_t a0, uint32_t a1,
                                         uint32_t a2, uint32_t a3,
                                         uint32_t b0, uint32_t b1) {
    asm volatile(
        "mma.sync.aligned.m16n8k16.row.col.f32.bf16.bf16.f32 "
        "{%0,%1,%2,%3}, {%4,%5,%6,%7}, {%8,%9}, {%0,%1,%2,%3};"
        : "+f"(c[0]), "+f"(c[1]), "+f"(c[2]), "+f"(c[3])
        : "r"(a0), "r"(a1), "r"(a2), "r"(a3), "r"(b0), "r"(b1));
}

__device__ __forceinline__ void ldsm_x4(uint32_t& r0, uint32_t& r1,
                                        uint32_t& r2, uint32_t& r3,
                                        uint32_t addr) {
    asm volatile("ldmatrix.sync.aligned.m8n8.x4.shared.b16 {%0,%1,%2,%3}, [%4];"
                 : "=r"(r0), "=r"(r1), "=r"(r2), "=r"(r3) : "r"(addr));
}

__device__ __forceinline__ float ex2_fast(float x) {
    float r;
    asm("ex2.approx.ftz.f32 %0, %1;" : "=f"(r) : "f"(x));
    return r;
}

// precise split (round-to-nearest hi) - used in prep only
__device__ __forceinline__ void splitpack(float e0, float e1,
                                          uint32_t& hi, uint32_t& lo) {
    __nv_bfloat16 h0 = __float2bfloat16_rn(e0);
    __nv_bfloat16 h1 = __float2bfloat16_rn(e1);
    float h0f = __bfloat162float(h0);
    float h1f = __bfloat162float(h1);
    __nv_bfloat16 l0 = __float2bfloat16_rn(e0 - h0f);
    __nv_bfloat16 l1 = __float2bfloat16_rn(e1 - h1f);
    hi = ((uint32_t)__bfloat16_as_ushort(h1) << 16) | __bfloat16_as_ushort(h0);
    lo = ((uint32_t)__bfloat16_as_ushort(l1) << 16) | __bfloat16_as_ushort(l0);
}

// fast truncation split
__device__ __forceinline__ void splitpack_fast(float e0, float e1,
                                               uint32_t& hi, uint32_t& lo) {
    uint32_t b0 = __float_as_uint(e0), b1 = __float_as_uint(e1);
    hi = __byte_perm(b0, b1, 0x7632);
    float l0f = e0 - __uint_as_float(b0 & 0xffff0000u);
    float l1f = e1 - __uint_as_float(b1 & 0xffff0000u);
    lo = __byte_perm(__float_as_uint(l0f), __float_as_uint(l1f), 0x7632);
}

// tanh-approx GELU with HW tanh (inputs small)
__device__ __forceinline__ float gelu_fast(float x) {
    float u = x * fmaf(0.0356774081f, x * x, 0.7978845608f);
    float t;
    asm("tanh.approx.f32 %0, %1;" : "=f"(t) : "f"(u));
    return 0.5f * x * (1.0f + t);
}

// decode unordered tile-pair index p in [0,528) -> (ta<=tb)
__device__ __forceinline__ void decode_pair(int p, int& ta, int& tb) {
    int a = 0, rem = NT;
    while (p >= rem) { p -= rem; rem--; a++; }
    ta = a; tb = a + p;
}

// ---------------------------------------------------------------------------
__global__ void mask_kernel(const float* __restrict__ nf) {
    int bn = blockIdx.x;
    const float4* p = (const float4*)(nf + (size_t)bn * FD);
    int nz = 0;
    for (int q = threadIdx.x; q < FD / 4; q += blockDim.x) {
        float4 v = p[q];
        nz |= (v.x != 0.0f) | (v.y != 0.0f) | (v.z != 0.0f) | (v.w != 0.0f);
    }
    int any = __syncthreads_or(nz);
    if (threadIdx.x == 0) g_pad[bn] = (any == 0) ? 1 : 0;
}

// ---------------------------------------------------------------------------
// pack w1^T / w2^T into mma B-fragment order (precise rn split; runs once)
// ---------------------------------------------------------------------------
__global__ void prep_kernel(const float* __restrict__ w1,
                            const float* __restrict__ w2) {
    int t = blockIdx.x * 256 + threadIdx.x;     // grid 16 x 256 = 4096
    {
        int idx = t;
        int s  = idx >> 9;
        int nb = (idx >> 5) & 15;
        int l  = idx & 31;
        int h  = nb * 8 + (l >> 2);
        int kp = s * 8 + (l & 3);
        float v0 = w1[(2 * kp) * 128 + h];
        float v1 = w1[(2 * kp + 1) * 128 + h];
        float v2 = w1[(2 * (kp + 4)) * 128 + h];
        float v3 = w1[(2 * (kp + 4) + 1) * 128 + h];
        uint32_t h0, l0, h1, l1;
        splitpack(v0, v1, h0, l0);
        splitpack(v2, v3, h1, l1);
        g_B1hi[idx] = make_uint2(h0, h1);
        g_B1lo[idx] = make_uint2(l0, l1);
    }
    if (t < 1024) {
        int idx = t;
        int s  = idx >> 7;
        int nb = (idx >> 5) & 3;
        int l  = idx & 31;
        int m  = nb * 8 + (l >> 2);
        int hp = s * 8 + (l & 3);
        float v0 = w2[(2 * hp) * 32 + m];
        float v1 = w2[(2 * hp + 1) * 32 + m];
        float v2 = w2[(2 * (hp + 4)) * 32 + m];
        float v3 = w2[(2 * (hp + 4) + 1) * 32 + m];
        uint32_t h0, l0, h1, l1;
        splitpack(v0, v1, h0, l0);
        splitpack(v2, v3, h1, l1);
        g_B2hi[idx] = make_uint2(h0, h1);
        g_B2lo[idx] = make_uint2(l0, l1);
    }
}

// ---------------------------------------------------------------------------
// main: block = (pairblock, b); 2 pair-tiles (8x8 pairs) per block = 128 rows
// ---------------------------------------------------------------------------
__global__ __launch_bounds__(256, 2)
void main_kernel(const float* __restrict__ pos,
                 const float* __restrict__ means,
                 const float* __restrict__ betas,
                 const float* __restrict__ b1,
                 const float* __restrict__ b2,
                 float* __restrict__ gab,
                 float* __restrict__ dpos)
{
    extern __shared__ char smem[];
    const uint32_t sbase = smem_u32(smem);
    uint32_t* Ghi  = (uint32_t*)(smem + GHIO);
    uint32_t* Glo  = (uint32_t*)(smem + GLOO);
    float*    Cst  = (float*)(smem + CSTO);
    float*    tsr  = (float*)(smem + TSOF);
    float*    kjs  = (float*)(smem + KJOF);
    float*    kis  = (float*)(smem + KIOF);
    int*      irr  = (int*)(smem + IROF);
    int*      jrr  = (int*)(smem + JROF);

    const int b    = blockIdx.y;
    const int tid  = threadIdx.x;
    const int w    = tid >> 5;
    const int lane = tid & 31;
    const int g    = lane >> 2;
    const int c4   = lane & 3;

    // decode this block's two pair-tiles
    int ta1, tb1, ta2, tb2;
    decode_pair(2 * blockIdx.x,     ta1, tb1);
    decode_pair(2 * blockIdx.x + 1, ta2, tb2);

    // ldmatrix per-lane address components (A / G operand pattern)
    const int lmat = lane >> 3, lrow = lane & 7;
    const int rowA = lrow + 8 * (lmat & 1);
    const int kaddA = (lmat >> 1) * 4;

    // ---- phase 0: per-row metadata, dpos (both orientations), t, keeps ----
    if (tid < 128) {
        int r    = tid;
        int tile = r >> 6;
        int ta = tile ? ta2 : ta1;
        int tb = tile ? tb2 : tb1;
        int ii = (r >> 3) & 7, jj = r & 7;
        int i = ta * 8 + ii, j = tb * 8 + jj;
        float pix = pos[(b * NN + i) * 3 + 0];
        float piy = pos[(b * NN + i) * 3 + 1];
        float piz = pos[(b * NN + i) * 3 + 2];
        float pjx = pos[(b * NN + j) * 3 + 0];
        float pjy = pos[(b * NN + j) * 3 + 1];
        float pjz = pos[(b * NN + j) * 3 + 2];
        float dx = pix - pjx, dy = piy - pjy, dz = piz - pjz;
        size_t d1 = (((size_t)(b * NN + i)) * NN + j) * 3;
        size_t d2 = (((size_t)(b * NN + j)) * NN + i) * 3;
        dpos[d1 + 0] = dx;  dpos[d1 + 1] = dy;  dpos[d1 + 2] = dz;
        dpos[d2 + 0] = -dx; dpos[d2 + 1] = -dy; dpos[d2 + 2] = -dz;
        float rr = dx * dx + dy * dy + dz * dz;
        float d = (rr > 0.0f) ? sqrtf(rr) : 0.0f;
        tsr[r] = expf(-d);              // precise
        kjs[r] = g_pad[b * NN + j] ? 0.0f : 1.0f;
        kis[r] = g_pad[b * NN + i] ? 0.0f : 1.0f;
        irr[r] = i;  jrr[r] = j;
    }
    __syncthreads();

    // ================= GEMM1: C1[128r x 128h] = ef @ w1 ====================
    const int wj = w & 1;    // 64 rows at wj*64
    const int wh = w >> 1;   // 32 cols at wh*32
    const int gkp = tid & 15;
    const int gjg = tid >> 4;           // tile*8 + ii ; owns rows gjg*8..+7
    const int gtile = gjg >> 3;
    const int gii = gjg & 7;
    const int gta = gtile ? ta2 : ta1;
    const int gtb = gtile ? tb2 : tb1;
    const bool gdiag = (gta == gtb);

    float acc[4][4][4];
#pragma unroll
    for (int mi = 0; mi < 4; mi++)
#pragma unroll
        for (int ni = 0; ni < 4; ni++)
#pragma unroll
            for (int q = 0; q < 4; q++) acc[mi][ni][q] = 0.0f;

    // ---- generate chunk 0 into buffer 0 ----
    {
        uint32_t* Ah = (uint32_t*)(smem + AHI0);
        uint32_t* Al = (uint32_t*)(smem + ALO0);
        float2* spB = (float2*)(smem + SPB0);
        int k0 = 2 * gkp;
        float nb0 = -betas[k0]     * 1.44269504088896f;
        float nb1 = -betas[k0 + 1] * 1.44269504088896f;
        float mk0 = means[k0], mk1 = means[k0 + 1];
        float s0 = 0.0f, s1 = 0.0f;
#pragma unroll
        for (int q = 0; q < 8; q++) {
            int r = gjg * 8 + q;
            float t  = tsr[r];
            float kj = kjs[r];
            float d0 = t - mk0, d1 = t - mk1;
            float e0 = ex2_fast(nb0 * d0 * d0);
            float e1 = ex2_fast(nb1 * d1 * d1);
            s0 += e0 * kj;  s1 += e1 * kj;
            uint32_t hi, lo;
            splitpack_fast(e0, e1, hi, lo);
            Ah[r * 20 + gkp] = hi;
            Al[r * 20 + gkp] = lo;
            if (!gdiag) {
                float ki = kis[r];
                spB[(gjg * 8 + q) * 16 + gkp] = make_float2(e0 * ki, e1 * ki);
            }
        }
        *(float2*)&g_parts[((((size_t)b * NT + gta) * NT + gtb) * 8 + gii) * 128
                           + 0 * 32 + 2 * gkp] = make_float2(s0, s1);
    }
    __syncthreads();

    // ============ pipelined K-chunk loop (4 chunks of 32 k) ================
    for (int kc = 0; kc < 4; kc++) {
        const int buf = kc & 1;
        const uint32_t uAhi = sbase + (buf ? AHI1 : AHI0);
        const uint32_t uAlo = uAhi + 10240;

        // ---- B-reduction for chunk kc: sum over ii per (tile,jj,k) ----
        {
            const float* spB = (const float*)(smem + (buf ? SPB1 : SPB0));
#pragma unroll
            for (int h = 0; h < 2; h++) {
                int s = h * 256 + tid;
                int stile = s >> 8;
                int sjj = (s >> 5) & 7;
                int sk  = s & 31;
                int sta = stile ? ta2 : ta1;
                int stb = stile ? tb2 : tb1;
                if (sta != stb) {
                    float a0 = 0.0f, a1 = 0.0f;
#pragma unroll
                    for (int ii2 = 0; ii2 < 8; ii2 += 2) {
                        a0 += spB[((stile * 8 + ii2) * 8 + sjj) * 32 + sk];
                        a1 += spB[((stile * 8 + ii2 + 1) * 8 + sjj) * 32 + sk];
                    }
                    g_parts[((((size_t)b * NT + stb) * NT + sta) * 8 + sjj) * 128
                            + kc * 32 + sk] = a0 + a1;
                }
            }
        }

        // ---- MMA: 2 k-steps of 16; B frags streamed from L2 ----
#pragma unroll
        for (int ks = 0; ks < 2; ks++) {
            int s = kc * 2 + ks;
            uint2 bh[4], bl[4];
#pragma unroll
            for (int ni = 0; ni < 4; ni++) {
                int idx = ((s * 16 + wh * 4 + ni) * 32) + lane;
                bh[ni] = g_B1hi[idx];
                bl[ni] = g_B1lo[idx];
            }
            int kloc = ks * 8;
#pragma unroll
            for (int mi = 0; mi < 4; mi++) {
                uint32_t aoff = (uint32_t)(((wj * 64 + mi * 16 + rowA) * 20
                                            + kloc + kaddA) * 4);
                uint32_t ah0, ah1, ah2, ah3, al0, al1, al2, al3;
                ldsm_x4(ah0, ah1, ah2, ah3, uAhi + aoff);
                ldsm_x4(al0, al1, al2, al3, uAlo + aoff);
#pragma unroll
                for (int ni = 0; ni < 4; ni++) {
                    mma_bf16(acc[mi][ni], ah0, ah1, ah2, ah3, bh[ni].x, bh[ni].y);
                    mma_bf16(acc[mi][ni], al0, al1, al2, al3, bh[ni].x, bh[ni].y);
                    mma_bf16(acc[mi][ni], ah0, ah1, ah2, ah3, bl[ni].x, bl[ni].y);
                }
            }
        }

        // ---- generate chunk kc+1 into other buffer (overlaps HMMA drain) --
        if (kc < 3) {
            uint32_t* Ah = (uint32_t*)(smem + ((buf ^ 1) ? AHI1 : AHI0));
            uint32_t* Al = (uint32_t*)(smem + ((buf ^ 1) ? ALO1 : ALO0));
            float2* spB = (float2*)(smem + ((buf ^ 1) ? SPB1 : SPB0));
            int k0 = (kc + 1) * 32 + 2 * gkp;
            float nb0 = -betas[k0]     * 1.44269504088896f;
            float nb1 = -betas[k0 + 1] * 1.44269504088896f;
            float mk0 = means[k0], mk1 = means[k0 + 1];
            float s0 = 0.0f, s1 = 0.0f;
#pragma unroll
            for (int q = 0; q < 8; q++) {
                int r = gjg * 8 + q;
                float t  = tsr[r];
                float kj = kjs[r];
                float d0 = t - mk0, d1 = t - mk1;
                float e0 = ex2_fast(nb0 * d0 * d0);
                float e1 = ex2_fast(nb1 * d1 * d1);
                s0 += e0 * kj;  s1 += e1 * kj;
                uint32_t hi, lo;
                splitpack_fast(e0, e1, hi, lo);
                Ah[r * 20 + gkp] = hi;
                Al[r * 20 + gkp] = lo;
                if (!gdiag) {
                    float ki = kis[r];
                    spB[(gjg * 8 + q) * 16 + gkp] = make_float2(e0 * ki, e1 * ki);
                }
            }
            *(float2*)&g_parts[((((size_t)b * NT + gta) * NT + gtb) * 8 + gii) * 128
                               + (kc + 1) * 32 + 2 * gkp] = make_float2(s0, s1);
        }
        __syncthreads();
    }

    // ---- epilogue1: +b1, fast GELU, split/pack into G (aliases A/spB) ----
    {
        float b1r0[4], b1r1[4];
#pragma unroll
        for (int ni = 0; ni < 4; ni++) {
            int h0 = wh * 32 + ni * 8 + c4 * 2;
            b1r0[ni] = b1[h0];
            b1r1[ni] = b1[h0 + 1];
        }
#pragma unroll
        for (int mi = 0; mi < 4; mi++) {
            int r0 = wj * 64 + mi * 16 + g;
            int r1 = r0 + 8;
#pragma unroll
            for (int ni = 0; ni < 4; ni++) {
                int hp = wh * 16 + ni * 4 + c4;
                float g00 = gelu_fast(acc[mi][ni][0] + b1r0[ni]);
                float g01 = gelu_fast(acc[mi][ni][1] + b1r1[ni]);
                float g10 = gelu_fast(acc[mi][ni][2] + b1r0[ni]);
                float g11 = gelu_fast(acc[mi][ni][3] + b1r1[ni]);
                uint32_t hi, lo;
                splitpack_fast(g00, g01, hi, lo);
                Ghi[r0 * 68 + hp] = hi;  Glo[r0 * 68 + hp] = lo;
                splitpack_fast(g10, g11, hi, lo);
                Ghi[r1 * 68 + hp] = hi;  Glo[r1 * 68 + hp] = lo;
            }
        }
    }
    __syncthreads();

    // ================= GEMM2: C2[128r x 32m] = G @ w2 ======================
    float acc2[4][4];
#pragma unroll
    for (int ni = 0; ni < 4; ni++)
#pragma unroll
        for (int q = 0; q < 4; q++) acc2[ni][q] = 0.0f;

    const int jt = w * 16;
#pragma unroll
    for (int s = 0; s < 8; s++) {
        uint32_t goff = (uint32_t)(((jt + rowA) * 68 + s * 8 + kaddA) * 4);
        uint32_t gh0, gh1, gh2, gh3, gl0, gl1, gl2, gl3;
        ldsm_x4(gh0, gh1, gh2, gh3, sbase + GHIO + goff);
        ldsm_x4(gl0, gl1, gl2, gl3, sbase + GLOO + goff);
        uint2 bh[4], bl[4];
#pragma unroll
        for (int ni = 0; ni < 4; ni++) {
            int idx = ((s * 4 + ni) * 32) + lane;
            bh[ni] = g_B2hi[idx];
            bl[ni] = g_B2lo[idx];
        }
#pragma unroll
        for (int ni = 0; ni < 4; ni++) {
            mma_bf16(acc2[ni], gh0, gh1, gh2, gh3, bh[ni].x, bh[ni].y);
            mma_bf16(acc2[ni], gl0, gl1, gl2, gl3, bh[ni].x, bh[ni].y);
            mma_bf16(acc2[ni], gh0, gh1, gh2, gh3, bl[ni].x, bl[ni].y);
        }
    }
    __syncthreads();   // G consumed; Cst may alias

    // ---- epilogue2: +b2 into staging ----
#pragma unroll
    for (int ni = 0; ni < 4; ni++) {
        int m0 = ni * 8 + c4 * 2;
        float e0 = b2[m0], e1 = b2[m0 + 1];
        int r0 = jt + g, r1 = r0 + 8;
        Cst[r0 * 37 + m0]     = acc2[ni][0] + e0;
        Cst[r0 * 37 + m0 + 1] = acc2[ni][1] + e1;
        Cst[r1 * 37 + m0]     = acc2[ni][2] + e0;
        Cst[r1 * 37 + m0 + 1] = acc2[ni][3] + e1;
    }
    __syncthreads();

    // ---- gab stores, orientation 1: [b][m][i][j], lanes vary jj ----
    {
        int jj = tid & 7, ii = (tid >> 3) & 7, tile = (tid >> 6) & 1;
        int mb = tid >> 7;
        int r = tile * 64 + ii * 8 + jj;
        int i = irr[r], j = jrr[r];
        bool pad = (kjs[r] == 0.0f);
#pragma unroll
        for (int it = 0; it < 16; it++) {
            int m = it * 2 + mb;
            float v = Cst[r * 37 + m];
            gab[(((size_t)(b * HH + m)) * NN + i) * NN + j] = pad ? -1e20f : v;
        }
    }
    // ---- gab stores, orientation 2: [b][m][j][i], lanes vary ii ----
    {
        int ii = tid & 7, jj = (tid >> 3) & 7, tile = (tid >> 6) & 1;
        int mb = tid >> 7;
        int r = tile * 64 + ii * 8 + jj;
        int i = irr[r], j = jrr[r];
        bool pad = (kis[r] == 0.0f);
#pragma unroll
        for (int it = 0; it < 16; it++) {
            int m = it * 2 + mb;
            float v = Cst[r * 37 + m];
            gab[(((size_t)(b * HH + m)) * NN + j) * NN + i] = pad ? -1e20f : v;
        }
    }
}

// ---------------------------------------------------------------------------
// merge_edge_features: assemble sum_ef from 32 tile-partials, then @ ew + eb
// grid (128 row-tiles of 16, 3 col-chunks); thread: 1 col x 16 rows
// ---------------------------------------------------------------------------
__global__ __launch_bounds__(256)
void merge_kernel(const float* __restrict__ ew,
                  const float* __restrict__ eb,
                  float* __restrict__ out)
{
    __shared__ float sef[16 * 128];
    const int r0  = blockIdx.x * 16;
    const int col = blockIdx.y * 256 + threadIdx.x;
    const int tid = threadIdx.x;

#pragma unroll
    for (int q = 0; q < 8; q++) {
        int s = q * 256 + tid;           // 2048 slots
        int r = s >> 7, k = s & 127;
        int gr = r0 + r;
        int b  = gr >> 8, iN = gr & 255;
        int ta = iN >> 3, ii = iN & 7;
        const float* p = &g_parts[((((size_t)b * NT + ta) * NT) * 8 + ii) * 128 + k];
        float a0 = 0.0f, a1 = 0.0f;
#pragma unroll
        for (int tb = 0; tb < 32; tb += 2) {
            a0 += p[(size_t)tb * 1024];
            a1 += p[(size_t)(tb + 1) * 1024];
        }
        sef[r * 128 + k] = a0 + a1;
    }
    __syncthreads();

    float acc[16];
    {
        float e = eb[col];
#pragma unroll
        for (int r = 0; r < 16; r++) acc[r] = e;
    }

    const float4* sef4 = (const float4*)sef;
#pragma unroll 2
    for (int k4 = 0; k4 < 32; k4++) {
        int k = k4 * 4;
        float v0 = ew[(size_t)(k + 0) * EMB + col];
        float v1 = ew[(size_t)(k + 1) * EMB + col];
        float v2 = ew[(size_t)(k + 2) * EMB + col];
        float v3 = ew[(size_t)(k + 3) * EMB + col];
#pragma unroll
        for (int r = 0; r < 16; r++) {
            float4 s = sef4[r * 32 + k4];
            acc[r] = fmaf(s.x, v0, acc[r]);
            acc[r] = fmaf(s.y, v1, acc[r]);
            acc[r] = fmaf(s.z, v2, acc[r]);
            acc[r] = fmaf(s.w, v3, acc[r]);
        }
    }

#pragma unroll
    for (int r = 0; r < 16; r++)
        out[(size_t)(r0 + r) * EMB + col] = acc[r];
}

// ---------------------------------------------------------------------------
extern "C" void kernel_launch(void* const* d_in, const int* in_sizes, int n_in,
                              void* d_out, int out_size) {
    const float* nf    = (const float*)d_in[0];
    const float* pos   = (const float*)d_in[1];
    const float* means = (const float*)d_in[2];
    const float* betas = (const float*)d_in[3];
    const float* w1    = (const float*)d_in[4];
    const float* b1    = (const float*)d_in[5];
    const float* w2    = (const float*)d_in[6];
    const float* b2    = (const float*)d_in[7];
    const float* ew    = (const float*)d_in[8];
    const float* eb    = (const float*)d_in[9];

    float* out  = (float*)d_out;
    float* gab  = out;
    float* mef  = out + GAB_ELEMS;
    float* dpos = out + GAB_ELEMS + MEF_ELEMS;

    cudaFuncSetAttribute(main_kernel,
                         cudaFuncAttributeMaxDynamicSharedMemorySize,
                         SMEM_TOTAL);

    prep_kernel<<<16, 256>>>(w1, w2);
    mask_kernel<<<BB * NN, 128>>>(nf);

    dim3 grid(NPAIR / 2, BB);           // 264 x 8 blocks
    main_kernel<<<grid, 256, SMEM_TOTAL>>>(
        pos, means, betas, b1, b2, gab, dpos);

    dim3 mgrid((BB * NN) / 16, 3);
    merge_kernel<<<mgrid, 256>>>(ew, eb, mef);
}

// round 17
// speedup vs baseline: 2.3684x; 1.0038x over previous
#include <cuda_runtime.h>
#include <cuda_bf16.h>
#include <math.h>
#include <stdint.h>

#define BB 8
#define NN 256
#define KK 128
#define HH 32
#define EMB 768
#define FD 768

#define GAB_ELEMS   (BB*HH*NN*NN)      // 16777216
#define MEF_ELEMS   (BB*NN*EMB)        // 1572864

#define NT   32      // number of 8-row tiles per dimension
#define NPAIR 528    // NT*(NT+1)/2

// scratch (no cudaMalloc allowed)
__device__ float g_parts[(size_t)BB * NT * NT * 8 * KK];  // [b][ta][tb][ii][k]
__device__ float g_sumef[BB * NN * KK];                   // [b][i][k]
__device__ int   g_pad[BB * NN];
// pre-packed mma B-fragments (bf16 hi/lo pairs), exact lane order
__device__ uint2 g_B1hi[4096], g_B1lo[4096];   // [(s*16+nb)*32 + lane]
__device__ uint2 g_B2hi[1024], g_B2lo[1024];   // [(s*4+nb)*32 + lane]

// ---------------------------------------------------------------------------
// SMEM layout (bytes), 256-thread block, 128 rows = 2 pair-tiles of 8x8 pairs
//   A[2]  : ef chunk bf16-pairs [128 r][20] hi/lo, double buffered (0..40960)
//   spB[2]: B-reduction dump, [2 tiles][8 ii][8 jj][16 kp] float2 (16K each)
//   G     : gelu bf16-pairs [128 r][68] hi/lo (0..69632, after chunks)
//   CST   : C2 staging fp32 [128 r][37] (over G-hi, after GEMM2)
// alias windows fenced by __syncthreads
// ---------------------------------------------------------------------------
#define AHI0   0         // 10240
#define ALO0   10240     // -> 20480
#define AHI1   20480
#define ALO1   30720     // -> 40960
#define SPB0   40960     // 16384 -> 57344
#define SPB1   57344     // 16384 -> 73728
#define GHIO   0         // 34816
#define GLOO   34816     // -> 69632
#define CSTO   0         // 18944
#define TSOF   73728     // 512  t per row
#define KJOF   74240     // 512  keep_j per row
#define KIOF   74752     // 512  keep_i per row
#define IROF   75264     // 512  i per row (int)
#define JROF   75776     // 512  j per row (int)
#define SMEM_TOTAL 76288

// ---------------------------------------------------------------------------
__device__ __forceinline__ uint32_t smem_u32(const void* p) {
    uint32_t a;
    asm("{ .reg .u64 t; cvta.to.shared.u64 t, %1; cvt.u32.u64 %0, t; }"
        : "=r"(a) : "l"(p));
    return a;
}

__device__ __forceinline__ void mma_bf16(float* c, uint32_t a0, uint32_t a1,
                                         uint32_t a2, uint32_t a3,
                                         uint32_t b0, uint32_t b1) {
    asm volatile(
        "mma.sync.aligned.m16n8k16.row.col.f32.bf16.bf16.f32 "
        "{%0,%1,%2,%3}, {%4,%5,%6,%7}, {%8,%9}, {%0,%1,%2,%3};"
        : "+f"(c[0]), "+f"(c[1]), "+f"(c[2]), "+f"(c[3])
        : "r"(a0), "r"(a1), "r"(a2), "r"(a3), "r"(b0), "r"(b1));
}

__device__ __forceinline__ void ldsm_x4(uint32_t& r0, uint32_t& r1,
                                        uint32_t& r2, uint32_t& r3,
                                        uint32_t addr) {
    asm volatile("ldmatrix.sync.aligned.m8n8.x4.shared.b16 {%0,%1,%2,%3}, [%4];"
                 : "=r"(r0), "=r"(r1), "=r"(r2), "=r"(r3) : "r"(addr));
}

__device__ __forceinline__ float ex2_fast(float x) {
    float r;
    asm("ex2.approx.ftz.f32 %0, %1;" : "=f"(r) : "f"(x));
    return r;
}

// precise split (round-to-nearest hi) - used in prep only
__device__ __forceinline__ void splitpack(float e0, float e1,
                                          uint32_t& hi, uint32_t& lo) {
    __nv_bfloat16 h0 = __float2bfloat16_rn(e0);
    __nv_bfloat16 h1 = __float2bfloat16_rn(e1);
    float h0f = __bfloat162float(h0);
    float h1f = __bfloat162float(h1);
    __nv_bfloat16 l0 = __float2bfloat16_rn(e0 - h0f);
    __nv_bfloat16 l1 = __float2bfloat16_rn(e1 - h1f);
    hi = ((uint32_t)__bfloat16_as_ushort(h1) << 16) | __bfloat16_as_ushort(h0);
    lo = ((uint32_t)__bfloat16_as_ushort(l1) << 16) | __bfloat16_as_ushort(l0);
}

// fast truncation split
__device__ __forceinline__ void splitpack_fast(float e0, float e1,
                                               uint32_t& hi, uint32_t& lo) {
    uint32_t b0 = __float_as_uint(e0), b1 = __float_as_uint(e1);
    hi = __byte_perm(b0, b1, 0x7632);
    float l0f = e0 - __uint_as_float(b0 & 0xffff0000u);
    float l1f = e1 - __uint_as_float(b1 & 0xffff0000u);
    lo = __byte_perm(__float_as_uint(l0f), __float_as_uint(l1f), 0x7632);
}

// tanh-approx GELU with HW tanh (inputs small)
__device__ __forceinline__ float gelu_fast(float x) {
    float u = x * fmaf(0.0356774081f, x * x, 0.7978845608f);
    float t;
    asm("tanh.approx.f32 %0, %1;" : "=f"(t) : "f"(u));
    return 0.5f * x * (1.0f + t);
}

// decode unordered tile-pair index p in [0,528) -> (ta<=tb)
__device__ __forceinline__ void decode_pair(int p, int& ta, int& tb) {
    int a = 0, rem = NT;
    while (p >= rem) { p -= rem; rem--; a++; }
    ta = a; tb = a + p;
}

// ---------------------------------------------------------------------------
__global__ void mask_kernel(const float* __restrict__ nf) {
    int bn = blockIdx.x;
    const float4* p = (const float4*)(nf + (size_t)bn * FD);
    int nz = 0;
    for (int q = threadIdx.x; q < FD / 4; q += blockDim.x) {
        float4 v = p[q];
        nz |= (v.x != 0.0f) | (v.y != 0.0f) | (v.z != 0.0f) | (v.w != 0.0f);
    }
    int any = __syncthreads_or(nz);
    if (threadIdx.x == 0) g_pad[bn] = (any == 0) ? 1 : 0;
}

// ---------------------------------------------------------------------------
// pack w1^T / w2^T into mma B-fragment order (precise rn split; runs once)
// ---------------------------------------------------------------------------
__global__ void prep_kernel(const float* __restrict__ w1,
                            const float* __restrict__ w2) {
    int t = blockIdx.x * 256 + threadIdx.x;     // grid 16 x 256 = 4096
    {
        int idx = t;
        int s  = idx >> 9;
        int nb = (idx >> 5) & 15;
        int l  = idx & 31;
        int h  = nb * 8 + (l >> 2);
        int kp = s * 8 + (l & 3);
        float v0 = w1[(2 * kp) * 128 + h];
        float v1 = w1[(2 * kp + 1) * 128 + h];
        float v2 = w1[(2 * (kp + 4)) * 128 + h];
        float v3 = w1[(2 * (kp + 4) + 1) * 128 + h];
        uint32_t h0, l0, h1, l1;
        splitpack(v0, v1, h0, l0);
        splitpack(v2, v3, h1, l1);
        g_B1hi[idx] = make_uint2(h0, h1);
        g_B1lo[idx] = make_uint2(l0, l1);
    }
    if (t < 1024) {
        int idx = t;
        int s  = idx >> 7;
        int nb = (idx >> 5) & 3;
        int l  = idx & 31;
        int m  = nb * 8 + (l >> 2);
        int hp = s * 8 + (l & 3);
        float v0 = w2[(2 * hp) * 32 + m];
        float v1 = w2[(2 * hp + 1) * 32 + m];
        float v2 = w2[(2 * (hp + 4)) * 32 + m];
        float v3 = w2[(2 * (hp + 4) + 1) * 32 + m];
        uint32_t h0, l0, h1, l1;
        splitpack(v0, v1, h0, l0);
        splitpack(v2, v3, h1, l1);
        g_B2hi[idx] = make_uint2(h0, h1);
        g_B2lo[idx] = make_uint2(l0, l1);
    }
}

// ---------------------------------------------------------------------------
// main: block = (pairblock, b); 2 pair-tiles (8x8 pairs) per block = 128 rows
// ---------------------------------------------------------------------------
__global__ __launch_bounds__(256, 2)
void main_kernel(const float* __restrict__ pos,
                 const float* __restrict__ means,
                 const float* __restrict__ betas,
                 const float* __restrict__ b1,
                 const float* __restrict__ b2,
                 float* __restrict__ gab,
                 float* __restrict__ dpos)
{
    extern __shared__ char smem[];
    const uint32_t sbase = smem_u32(smem);
    uint32_t* Ghi  = (uint32_t*)(smem + GHIO);
    uint32_t* Glo  = (uint32_t*)(smem + GLOO);
    float*    Cst  = (float*)(smem + CSTO);
    float*    tsr  = (float*)(smem + TSOF);
    float*    kjs  = (float*)(smem + KJOF);
    float*    kis  = (float*)(smem + KIOF);
    int*      irr  = (int*)(smem + IROF);
    int*      jrr  = (int*)(smem + JROF);

    const int b    = blockIdx.y;
    const int tid  = threadIdx.x;
    const int w    = tid >> 5;
    const int lane = tid & 31;
    const int g    = lane >> 2;
    const int c4   = lane & 3;

    // decode this block's two pair-tiles
    int ta1, tb1, ta2, tb2;
    decode_pair(2 * blockIdx.x,     ta1, tb1);
    decode_pair(2 * blockIdx.x + 1, ta2, tb2);

    // ldmatrix per-lane address components (A / G operand pattern)
    const int lmat = lane >> 3, lrow = lane & 7;
    const int rowA = lrow + 8 * (lmat & 1);
    const int kaddA = (lmat >> 1) * 4;

    // ---- phase 0: per-row metadata, dpos (both orientations), t, keeps ----
    if (tid < 128) {
        int r    = tid;
        int tile = r >> 6;
        int ta = tile ? ta2 : ta1;
        int tb = tile ? tb2 : tb1;
        int ii = (r >> 3) & 7, jj = r & 7;
        int i = ta * 8 + ii, j = tb * 8 + jj;
        float pix = pos[(b * NN + i) * 3 + 0];
        float piy = pos[(b * NN + i) * 3 + 1];
        float piz = pos[(b * NN + i) * 3 + 2];
        float pjx = pos[(b * NN + j) * 3 + 0];
        float pjy = pos[(b * NN + j) * 3 + 1];
        float pjz = pos[(b * NN + j) * 3 + 2];
        float dx = pix - pjx, dy = piy - pjy, dz = piz - pjz;
        size_t d1 = (((size_t)(b * NN + i)) * NN + j) * 3;
        size_t d2 = (((size_t)(b * NN + j)) * NN + i) * 3;
        dpos[d1 + 0] = dx;  dpos[d1 + 1] = dy;  dpos[d1 + 2] = dz;
        dpos[d2 + 0] = -dx; dpos[d2 + 1] = -dy; dpos[d2 + 2] = -dz;
        float rr = dx * dx + dy * dy + dz * dz;
        float d = (rr > 0.0f) ? sqrtf(rr) : 0.0f;
        tsr[r] = expf(-d);              // precise
        kjs[r] = g_pad[b * NN + j] ? 0.0f : 1.0f;
        kis[r] = g_pad[b * NN + i] ? 0.0f : 1.0f;
        irr[r] = i;  jrr[r] = j;
    }
    __syncthreads();

    // ================= GEMM1: C1[128r x 128h] = ef @ w1 ====================
    const int wj = w & 1;    // 64 rows at wj*64
    const int wh = w >> 1;   // 32 cols at wh*32
    const int gkp = tid & 15;
    const int gjg = tid >> 4;           // tile*8 + ii ; owns rows gjg*8..+7
    const int gtile = gjg >> 3;
    const int gii = gjg & 7;
    const int gta = gtile ? ta2 : ta1;
    const int gtb = gtile ? tb2 : tb1;
    const bool gdiag = (gta == gtb);

    float acc[4][4][4];
#pragma unroll
    for (int mi = 0; mi < 4; mi++)
#pragma unroll
        for (int ni = 0; ni < 4; ni++)
#pragma unroll
            for (int q = 0; q < 4; q++) acc[mi][ni][q] = 0.0f;

    // ---- generate chunk 0 into buffer 0 ----
    {
        uint32_t* Ah = (uint32_t*)(smem + AHI0);
        uint32_t* Al = (uint32_t*)(smem + ALO0);
        float2* spB = (float2*)(smem + SPB0);
        int k0 = 2 * gkp;
        float nb0 = -betas[k0]     * 1.44269504088896f;
        float nb1 = -betas[k0 + 1] * 1.44269504088896f;
        float mk0 = means[k0], mk1 = means[k0 + 1];
        float s0 = 0.0f, s1 = 0.0f;
#pragma unroll
        for (int q = 0; q < 8; q++) {
            int r = gjg * 8 + q;
            float t  = tsr[r];
            float kj = kjs[r];
            float d0 = t - mk0, d1 = t - mk1;
            float e0 = ex2_fast(nb0 * d0 * d0);
            float e1 = ex2_fast(nb1 * d1 * d1);
            s0 += e0 * kj;  s1 += e1 * kj;
            uint32_t hi, lo;
            splitpack_fast(e0, e1, hi, lo);
            Ah[r * 20 + gkp] = hi;
            Al[r * 20 + gkp] = lo;
            if (!gdiag) {
                float ki = kis[r];
                spB[(gjg * 8 + q) * 16 + gkp] = make_float2(e0 * ki, e1 * ki);
            }
        }
        *(float2*)&g_parts[((((size_t)b * NT + gta) * NT + gtb) * 8 + gii) * 128
                           + 0 * 32 + 2 * gkp] = make_float2(s0, s1);
    }
    __syncthreads();

    // ============ pipelined K-chunk loop (4 chunks of 32 k) ================
    for (int kc = 0; kc < 4; kc++) {
        const int buf = kc & 1;
        const uint32_t uAhi = sbase + (buf ? AHI1 : AHI0);
        const uint32_t uAlo = uAhi + 10240;

        // ---- B-reduction for chunk kc: sum over ii per (tile,jj,k) ----
        {
            const float* spB = (const float*)(smem + (buf ? SPB1 : SPB0));
#pragma unroll
            for (int h = 0; h < 2; h++) {
                int s = h * 256 + tid;
                int stile = s >> 8;
                int sjj = (s >> 5) & 7;
                int sk  = s & 31;
                int sta = stile ? ta2 : ta1;
                int stb = stile ? tb2 : tb1;
                if (sta != stb) {
                    float a0 = 0.0f, a1 = 0.0f;
#pragma unroll
                    for (int ii2 = 0; ii2 < 8; ii2 += 2) {
                        a0 += spB[((stile * 8 + ii2) * 8 + sjj) * 32 + sk];
                        a1 += spB[((stile * 8 + ii2 + 1) * 8 + sjj) * 32 + sk];
                    }
                    g_parts[((((size_t)b * NT + stb) * NT + sta) * 8 + sjj) * 128
                            + kc * 32 + sk] = a0 + a1;
                }
            }
        }

        // ---- MMA: 2 k-steps of 16; B frags streamed from L2 ----
#pragma unroll
        for (int ks = 0; ks < 2; ks++) {
            int s = kc * 2 + ks;
            uint2 bh[4], bl[4];
#pragma unroll
            for (int ni = 0; ni < 4; ni++) {
                int idx = ((s * 16 + wh * 4 + ni) * 32) + lane;
                bh[ni] = g_B1hi[idx];
                bl[ni] = g_B1lo[idx];
            }
            int kloc = ks * 8;
#pragma unroll
            for (int mi = 0; mi < 4; mi++) {
                uint32_t aoff = (uint32_t)(((wj * 64 + mi * 16 + rowA) * 20
                                            + kloc + kaddA) * 4);
                uint32_t ah0, ah1, ah2, ah3, al0, al1, al2, al3;
                ldsm_x4(ah0, ah1, ah2, ah3, uAhi + aoff);
                ldsm_x4(al0, al1, al2, al3, uAlo + aoff);
#pragma unroll
                for (int ni = 0; ni < 4; ni++) {
                    mma_bf16(acc[mi][ni], ah0, ah1, ah2, ah3, bh[ni].x, bh[ni].y);
                    mma_bf16(acc[mi][ni], al0, al1, al2, al3, bh[ni].x, bh[ni].y);
                    mma_bf16(acc[mi][ni], ah0, ah1, ah2, ah3, bl[ni].x, bl[ni].y);
                }
            }
        }

        // ---- generate chunk kc+1 into other buffer (overlaps HMMA drain) --
        if (kc < 3) {
            uint32_t* Ah = (uint32_t*)(smem + ((buf ^ 1) ? AHI1 : AHI0));
            uint32_t* Al = (uint32_t*)(smem + ((buf ^ 1) ? ALO1 : ALO0));
            float2* spB = (float2*)(smem + ((buf ^ 1) ? SPB1 : SPB0));
            int k0 = (kc + 1) * 32 + 2 * gkp;
            float nb0 = -betas[k0]     * 1.44269504088896f;
            float nb1 = -betas[k0 + 1] * 1.44269504088896f;
            float mk0 = means[k0], mk1 = means[k0 + 1];
            float s0 = 0.0f, s1 = 0.0f;
#pragma unroll
            for (int q = 0; q < 8; q++) {
                int r = gjg * 8 + q;
                float t  = tsr[r];
                float kj = kjs[r];
                float d0 = t - mk0, d1 = t - mk1;
                float e0 = ex2_fast(nb0 * d0 * d0);
                float e1 = ex2_fast(nb1 * d1 * d1);
                s0 += e0 * kj;  s1 += e1 * kj;
                uint32_t hi, lo;
                splitpack_fast(e0, e1, hi, lo);
                Ah[r * 20 + gkp] = hi;
                Al[r * 20 + gkp] = lo;
                if (!gdiag) {
                    float ki = kis[r];
                    spB[(gjg * 8 + q) * 16 + gkp] = make_float2(e0 * ki, e1 * ki);
                }
            }
            *(float2*)&g_parts[((((size_t)b * NT + gta) * NT + gtb) * 8 + gii) * 128
                               + (kc + 1) * 32 + 2 * gkp] = make_float2(s0, s1);
        }
        __syncthreads();
    }

    // ---- epilogue1: +b1, fast GELU, split/pack into G (aliases A/spB) ----
    {
        float b1r0[4], b1r1[4];
#pragma unroll
        for (int ni = 0; ni < 4; ni++) {
            int h0 = wh * 32 + ni * 8 + c4 * 2;
            b1r0[ni] = b1[h0];
            b1r1[ni] = b1[h0 + 1];
        }
#pragma unroll
        for (int mi = 0; mi < 4; mi++) {
            int r0 = wj * 64 + mi * 16 + g;
            int r1 = r0 + 8;
#pragma unroll
            for (int ni = 0; ni < 4; ni++) {
                int hp = wh * 16 + ni * 4 + c4;
                float g00 = gelu_fast(acc[mi][ni][0] + b1r0[ni]);
                float g01 = gelu_fast(acc[mi][ni][1] + b1r1[ni]);
                float g10 = gelu_fast(acc[mi][ni][2] + b1r0[ni]);
                float g11 = gelu_fast(acc[mi][ni][3] + b1r1[ni]);
                uint32_t hi, lo;
                splitpack_fast(g00, g01, hi, lo);
                Ghi[r0 * 68 + hp] = hi;  Glo[r0 * 68 + hp] = lo;
                splitpack_fast(g10, g11, hi, lo);
                Ghi[r1 * 68 + hp] = hi;  Glo[r1 * 68 + hp] = lo;
            }
        }
    }
    __syncthreads();

    // ================= GEMM2: C2[128r x 32m] = G @ w2 ======================
    float acc2[4][4];
#pragma unroll
    for (int ni = 0; ni < 4; ni++)
#pragma unroll
        for (int q = 0; q < 4; q++) acc2[ni][q] = 0.0f;

    const int jt = w * 16;
#pragma unroll
    for (int s = 0; s < 8; s++) {
        uint32_t goff = (uint32_t)(((jt + rowA) * 68 + s * 8 + kaddA) * 4);
        uint32_t gh0, gh1, gh2, gh3, gl0, gl1, gl2, gl3;
        ldsm_x4(gh0, gh1, gh2, gh3, sbase + GHIO + goff);
        ldsm_x4(gl0, gl1, gl2, gl3, sbase + GLOO + goff);
        uint2 bh[4], bl[4];
#pragma unroll
        for (int ni = 0; ni < 4; ni++) {
            int idx = ((s * 4 + ni) * 32) + lane;
            bh[ni] = g_B2hi[idx];
            bl[ni] = g_B2lo[idx];
        }
#pragma unroll
        for (int ni = 0; ni < 4; ni++) {
            mma_bf16(acc2[ni], gh0, gh1, gh2, gh3, bh[ni].x, bh[ni].y);
            mma_bf16(acc2[ni], gl0, gl1, gl2, gl3, bh[ni].x, bh[ni].y);
            mma_bf16(acc2[ni], gh0, gh1, gh2, gh3, bl[ni].x, bl[ni].y);
        }
    }
    __syncthreads();   // G consumed; Cst may alias

    // ---- epilogue2: +b2 into staging ----
#pragma unroll
    for (int ni = 0; ni < 4; ni++) {
        int m0 = ni * 8 + c4 * 2;
        float e0 = b2[m0], e1 = b2[m0 + 1];
        int r0 = jt + g, r1 = r0 + 8;
        Cst[r0 * 37 + m0]     = acc2[ni][0] + e0;
        Cst[r0 * 37 + m0 + 1] = acc2[ni][1] + e1;
        Cst[r1 * 37 + m0]     = acc2[ni][2] + e0;
        Cst[r1 * 37 + m0 + 1] = acc2[ni][3] + e1;
    }
    __syncthreads();

    // ---- gab stores, orientation 1: [b][m][i][j], lanes vary jj ----
    {
        int jj = tid & 7, ii = (tid >> 3) & 7, tile = (tid >> 6) & 1;
        int mb = tid >> 7;
        int r = tile * 64 + ii * 8 + jj;
        int i = irr[r], j = jrr[r];
        bool pad = (kjs[r] == 0.0f);
#pragma unroll
        for (int it = 0; it < 16; it++) {
            int m = it * 2 + mb;
            float v = Cst[r * 37 + m];
            gab[(((size_t)(b * HH + m)) * NN + i) * NN + j] = pad ? -1e20f : v;
        }
    }
    // ---- gab stores, orientation 2: [b][m][j][i], lanes vary ii ----
    {
        int ii = tid & 7, jj = (tid >> 3) & 7, tile = (tid >> 6) & 1;
        int mb = tid >> 7;
        int r = tile * 64 + ii * 8 + jj;
        int i = irr[r], j = jrr[r];
        bool pad = (kis[r] == 0.0f);
#pragma unroll
        for (int it = 0; it < 16; it++) {
            int m = it * 2 + mb;
            float v = Cst[r * 37 + m];
            gab[(((size_t)(b * HH + m)) * NN + j) * NN + i] = pad ? -1e20f : v;
        }
    }
}

// ---------------------------------------------------------------------------
// stage A: reduce g_parts over tb -> g_sumef[b][i][k]  (262144 outputs)
// grid 1024 x 256; 1 output/thread; 32 independent coalesced LDGs (high MLP)
// ---------------------------------------------------------------------------
__global__ __launch_bounds__(256)
void reduce_kernel()
{
    int gid = blockIdx.x * 256 + threadIdx.x;
    int k = gid & 127;
    int i = (gid >> 7) & 255;
    int b = gid >> 15;
    int ta = i >> 3, ii = i & 7;
    const float* p = &g_parts[((((size_t)b * NT + ta) * NT) * 8 + ii) * 128 + k];
    float a0 = 0.0f, a1 = 0.0f, a2 = 0.0f, a3 = 0.0f;
#pragma unroll
    for (int tb = 0; tb < NT; tb += 4) {
        a0 += p[(size_t)tb * 1024];
        a1 += p[(size_t)(tb + 1) * 1024];
        a2 += p[(size_t)(tb + 2) * 1024];
        a3 += p[(size_t)(tb + 3) * 1024];
    }
    g_sumef[gid] = (a0 + a1) + (a2 + a3);
}

// ---------------------------------------------------------------------------
// merge_edge_features = g_sumef @ ew + eb
// grid (128 row-tiles, 3 col-chunks); thread: 1 col x 16 rows; float4 sef
// ---------------------------------------------------------------------------
__global__ __launch_bounds__(256)
void merge_kernel(const float* __restrict__ ew,
                  const float* __restrict__ eb,
                  float* __restrict__ out)
{
    __shared__ float sef[16 * 128];
    const int r0  = blockIdx.x * 16;
    const int col = blockIdx.y * 256 + threadIdx.x;
    const int tid = threadIdx.x;

#pragma unroll
    for (int q = 0; q < 8; q++)
        sef[tid + 256 * q] = g_sumef[(size_t)r0 * 128 + tid + 256 * q];
    __syncthreads();

    float acc[16];
    {
        float e = eb[col];
#pragma unroll
        for (int r = 0; r < 16; r++) acc[r] = e;
    }

    const float4* sef4 = (const float4*)sef;
#pragma unroll 2
    for (int k4 = 0; k4 < 32; k4++) {
        int k = k4 * 4;
        float v0 = ew[(size_t)(k + 0) * EMB + col];
        float v1 = ew[(size_t)(k + 1) * EMB + col];
        float v2 = ew[(size_t)(k + 2) * EMB + col];
        float v3 = ew[(size_t)(k + 3) * EMB + col];
#pragma unroll
        for (int r = 0; r < 16; r++) {
            float4 s = sef4[r * 32 + k4];
            acc[r] = fmaf(s.x, v0, acc[r]);
            acc[r] = fmaf(s.y, v1, acc[r]);
            acc[r] = fmaf(s.z, v2, acc[r]);
            acc[r] = fmaf(s.w, v3, acc[r]);
        }
    }

#pragma unroll
    for (int r = 0; r < 16; r++)
        out[(size_t)(r0 + r) * EMB + col] = acc[r];
}

// ---------------------------------------------------------------------------
extern "C" void kernel_launch(void* const* d_in, const int* in_sizes, int n_in,
                              void* d_out, int out_size) {
    const float* nf    = (const float*)d_in[0];
    const float* pos   = (const float*)d_in[1];
    const float* means = (const float*)d_in[2];
    const float* betas = (const float*)d_in[3];
    const float* w1    = (const float*)d_in[4];
    const float* b1    = (const float*)d_in[5];
    const float* w2    = (const float*)d_in[6];
    const float* b2    = (const float*)d_in[7];
    const float* ew    = (const float*)d_in[8];
    const float* eb    = (const float*)d_in[9];

    float* out  = (float*)d_out;
    float* gab  = out;
    float* mef  = out + GAB_ELEMS;
    float* dpos = out + GAB_ELEMS + MEF_ELEMS;

    cudaFuncSetAttribute(main_kernel,
                         cudaFuncAttributeMaxDynamicSharedMemorySize,
                         SMEM_TOTAL);

    prep_kernel<<<16, 256>>>(w1, w2);
    mask_kernel<<<BB * NN, 128>>>(nf);

    dim3 grid(NPAIR / 2, BB);           // 264 x 8 blocks
    main_kernel<<<grid, 256, SMEM_TOTAL>>>(
        pos, means, betas, b1, b2, gab, dpos);

    reduce_kernel<<<(BB * NN * KK) / 256, 256>>>();

    dim3 mgrid((BB * NN) / 16, 3);
    merge_kernel<<<mgrid, 256>>>(ew, eb, mef);
}